// round 12
// baseline (speedup 1.0000x reference)
#include <cuda_runtime.h>
#include <math.h>

#define Nn 100000
#define Ee 1600000
#define Hh 64
#define Ll 3
#define Kt 8192
#define CUT 5.0f
#define INVBN 0.9995003747f   // 1/sqrt(1+1e-3)
#define NB1 98                // ceil(Nn/1024) scan blocks

typedef unsigned long long ull;

// ---- static device scratch ----
__device__ __align__(256) float g_h[Nn * Hh];       // node features, 25.6 MB
__device__ __align__(256) float g_agg[Nn * Hh];     // aggregation target, 25.6 MB
__device__ __align__(256) int4  g_ep4[Ee];          // (col, fs0, fs1, fs2), 25.6 MB
__device__ int   g_cnt[Nn];
__device__ int   g_off[Nn];
__device__ int   g_cur[Nn];
__device__ ull   g_state[NB1];                      // lookback scan states
__device__ float g_table[Ll * Kt];
__device__ float g_mean[Hh];

__device__ __forceinline__ float sp(float x) {      // softplus, stable
    return fmaxf(x, 0.0f) + log1pf(expf(-fabsf(x)));
}

// ---- f32x2 helpers ----
__device__ __forceinline__ ull pk2(float a, float b) {
    ull r; asm("mov.b64 %0,{%1,%2};" : "=l"(r) : "f"(a), "f"(b)); return r;
}
__device__ __forceinline__ float2 up2(ull v) {
    float2 f; asm("mov.b64 {%0,%1},%2;" : "=f"(f.x), "=f"(f.y) : "l"(v)); return f;
}
__device__ __forceinline__ ull fma2(ull a, ull b, ull c) {
    ull d; asm("fma.rn.f32x2 %0,%1,%2,%3;" : "=l"(d) : "l"(a), "l"(b), "l"(c)); return d;
}

// ---- table: fs(d)*cut(d); fW2 rowsums computed per-block in smem ----
__global__ void table_kernel(const float* __restrict__ fW1,
                             const float* __restrict__ fb1,
                             const float* __restrict__ fW2,
                             const float* __restrict__ fb2) {
    int t = blockIdx.x * 256 + threadIdx.x;       // grid 96x256 == Ll*Kt
    int l = t >> 13;                              // same l for whole block
    __shared__ float sw2[64];
    __shared__ float sb2;
    if (threadIdx.x < 64) {
        const float* p = fW2 + l * Hh * Hh + threadIdx.x * Hh;
        float s = 0.0f;
        #pragma unroll
        for (int k = 0; k < Hh; k++) s += p[k];
        sw2[threadIdx.x] = s;
    }
    if (threadIdx.x == 64) {
        float s = 0.0f;
        for (int k = 0; k < Hh; k++) s += fb2[l * Hh + k];
        sb2 = s;
    }
    __syncthreads();
    int k = t & (Kt - 1);
    float d = k * (CUT / (float)(Kt - 1));
    float s = d * (2.0f / CUT) - 1.0f;
    const float* w1 = fW1 + l * Hh;
    const float* b1 = fb1 + l * Hh;
    float acc = sb2;
    #pragma unroll 8
    for (int j = 0; j < Hh; j++)
        acc = fmaf(tanhf(fmaf(s, w1[j], b1[j])), sw2[j], acc);
    float cut = 0.5f * (cosf(d * (float)(M_PI / 5.0)) + 1.0f);
    g_table[t] = acc * cut;
}

// ---- embedding: h = x @ emb_W + emb_b ; also zero cnt/mean/scan-state ----
__global__ void embed_kernel(const float* __restrict__ x,
                             const float* __restrict__ W,
                             const float* __restrict__ b) {
    __shared__ float sW[16 * 64];
    __shared__ float sb[64];
    int tid = threadIdx.x;
    for (int i = tid; i < 16 * 64; i += 256) sW[i] = W[i];
    if (tid < 64) sb[tid] = b[tid];
    __syncthreads();
    int t = blockIdx.x * 256 + tid;
    // side duties (disjoint ranges, cheap)
    if (t < Nn) g_cnt[t] = 0;
    if (t < Hh) g_mean[t] = 0.0f;
    if (t < NB1) g_state[t] = 0ull;
    if (t >= Nn * 16) return;
    int n = t >> 4, q = t & 15, j0 = q * 4;
    const float* xr = x + n * 16;
    float4 acc = make_float4(sb[j0], sb[j0 + 1], sb[j0 + 2], sb[j0 + 3]);
    #pragma unroll
    for (int i = 0; i < 16; i++) {
        float xi = xr[i];
        acc.x = fmaf(xi, sW[i * 64 + j0 + 0], acc.x);
        acc.y = fmaf(xi, sW[i * 64 + j0 + 1], acc.y);
        acc.z = fmaf(xi, sW[i * 64 + j0 + 2], acc.z);
        acc.w = fmaf(xi, sW[i * 64 + j0 + 3], acc.w);
    }
    ((float4*)g_h)[t] = acc;
}

__global__ void hist_kernel(const int* __restrict__ eidx) {
    int e = blockIdx.x * blockDim.x + threadIdx.x;
    if (e < Ee) atomicAdd(&g_cnt[eidx[e]], 1);
}

// ---- single-pass decoupled-lookback exclusive scan of g_cnt -> g_off/g_cur ----
__global__ void __launch_bounds__(1024) scan_kernel() {
    int bid = blockIdx.x;
    int i = bid * 1024 + threadIdx.x;
    int v = (i < Nn) ? g_cnt[i] : 0;
    int lane = threadIdx.x & 31, w = threadIdx.x >> 5;
    int x = v;
    #pragma unroll
    for (int off = 1; off < 32; off <<= 1) {
        int y = __shfl_up_sync(0xffffffff, x, off);
        if (lane >= off) x += y;
    }
    __shared__ int wsum[32], wpre[32];
    __shared__ int stotal, sprefix;
    if (lane == 31) wsum[w] = x;
    __syncthreads();
    if (threadIdx.x < 32) {
        int s = wsum[threadIdx.x];
        int xs = s;
        #pragma unroll
        for (int off = 1; off < 32; off <<= 1) {
            int y = __shfl_up_sync(0xffffffff, xs, off);
            if ((int)threadIdx.x >= off) xs += y;
        }
        wpre[threadIdx.x] = xs - s;
        if (threadIdx.x == 31) stotal = xs;
    }
    __syncthreads();
    int total = stotal;
    if (threadIdx.x == 0) {
        if (bid == 0) {
            sprefix = 0;
            atomicExch(&g_state[0], (2ull << 32) | (unsigned)total);
        } else {
            atomicExch(&g_state[bid], (1ull << 32) | (unsigned)total);
            ull run = 0;
            int p = bid - 1;
            while (true) {
                ull sv = atomicAdd(&g_state[p], 0ull);
                unsigned st = (unsigned)(sv >> 32);
                if (st == 0u) { __nanosleep(32); continue; }
                run += (unsigned)sv;
                if (st == 2u) break;
                p--;
            }
            sprefix = (int)run;
            atomicExch(&g_state[bid], (2ull << 32) | (unsigned)(run + total));
        }
    }
    __syncthreads();
    if (i < Nn) {
        int o = x - v + wpre[w] + sprefix;
        g_off[i] = o;
        g_cur[i] = o;
    }
}

// scatter edges into CSR order; one int4 record (col, fs0, fs1, fs2)
__global__ void fill_kernel(const int* __restrict__ eidx,
                            const float* __restrict__ dist) {
    int e = blockIdx.x * blockDim.x + threadIdx.x;
    if (e >= Ee) return;
    int r = eidx[e];
    int c = eidx[Ee + e];
    float d = __ldg(dist + e);
    float u = d * ((float)(Kt - 1) / CUT);
    u = fminf(fmaxf(u, 0.0f), (float)(Kt - 2) + 0.999f);
    int i = (int)u;
    float fr = u - (float)i;
    float fs[Ll];
    #pragma unroll
    for (int l = 0; l < Ll; l++) {
        const float* tb = g_table + l * Kt;
        float t0 = __ldg(tb + i), t1 = __ldg(tb + i + 1);
        fs[l] = fmaf(fr, t1 - t0, t0);
    }
    int pos = atomicAdd(&g_cur[r], 1);
    g_ep4[pos] = make_int4(c, __float_as_int(fs[0]),
                           __float_as_int(fs[1]), __float_as_int(fs[2]));
}

// ============ per-layer edge aggregation: warp per row, whole-warp per edge ====
// (R10 proven form -- DO NOT TOUCH)
__global__ void __launch_bounds__(256) agg_kernel(int l) {
    int gw = (blockIdx.x * 256 + threadIdx.x) >> 5;
    if (gw >= Nn) return;
    int lane = threadIdx.x & 31;
    int beg = g_off[gw], deg = g_cnt[gw];
    float2 acc = make_float2(0.0f, 0.0f);
    const float2* hb = (const float2*)g_h;
    for (int base = 0; base < deg; base += 32) {
        int rem = deg - base;
        if (rem > 32) rem = 32;
        int col_r = 0, fs_r = 0;
        if (lane < rem) {
            int4 m = __ldg(&g_ep4[beg + base + lane]);
            col_r = m.x;
            fs_r = (l == 0) ? m.y : (l == 1 ? m.z : m.w);
        }
        int d = 0;
        #pragma unroll 4
        for (; d + 4 <= rem; d += 4) {
            int c0 = __shfl_sync(0xffffffff, col_r, d + 0);
            int c1 = __shfl_sync(0xffffffff, col_r, d + 1);
            int c2 = __shfl_sync(0xffffffff, col_r, d + 2);
            int c3 = __shfl_sync(0xffffffff, col_r, d + 3);
            float f0 = __int_as_float(__shfl_sync(0xffffffff, fs_r, d + 0));
            float f1 = __int_as_float(__shfl_sync(0xffffffff, fs_r, d + 1));
            float f2 = __int_as_float(__shfl_sync(0xffffffff, fs_r, d + 2));
            float f3 = __int_as_float(__shfl_sync(0xffffffff, fs_r, d + 3));
            float2 v0 = __ldg(hb + c0 * 32 + lane);
            float2 v1 = __ldg(hb + c1 * 32 + lane);
            float2 v2 = __ldg(hb + c2 * 32 + lane);
            float2 v3 = __ldg(hb + c3 * 32 + lane);
            acc.x = fmaf(v0.x, f0, acc.x);
            acc.y = fmaf(v0.y, f0, acc.y);
            acc.x = fmaf(v1.x, f1, acc.x);
            acc.y = fmaf(v1.y, f1, acc.y);
            acc.x = fmaf(v2.x, f2, acc.x);
            acc.y = fmaf(v2.y, f2, acc.y);
            acc.x = fmaf(v3.x, f3, acc.x);
            acc.y = fmaf(v3.y, f3, acc.y);
        }
        for (; d < rem; d++) {
            int c0 = __shfl_sync(0xffffffff, col_r, d);
            float f0 = __int_as_float(__shfl_sync(0xffffffff, fs_r, d));
            float2 v0 = __ldg(hb + c0 * 32 + lane);
            acc.x = fmaf(v0.x, f0, acc.x);
            acc.y = fmaf(v0.y, f0, acc.y);
        }
    }
    ((float2*)g_agg)[gw * 32 + lane] = acc;
}

// ===== node MLP: f32x2 packed weights, thread-per-column, 8 nodes/iter ========
__global__ void __launch_bounds__(128, 2) node_kernel(
    const float* __restrict__ iW1, const float* __restrict__ ib1,
    const float* __restrict__ iW2, const float* __restrict__ ib2,
    const float* __restrict__ gam, const float* __restrict__ bet,
    int do_mean) {
    __shared__ __align__(16) float sa[8][64];
    __shared__ __align__(16) float st[8][64];
    __shared__ float sm[128];
    int tid = threadIdx.x;
    int half = tid >> 6, j = tid & 63;
    ull w1[32], w2[32];
    #pragma unroll
    for (int p = 0; p < 32; p++) {
        w1[p] = pk2(iW1[(2 * p) * 64 + j], iW1[(2 * p + 1) * 64 + j]);
        w2[p] = pk2(iW2[(2 * p) * 64 + j], iW2[(2 * p + 1) * 64 + j]);
    }
    float b1 = ib1[j], b2 = ib2[j];
    float gm = gam[j] * INVBN, bt = bet[j];
    float ms = 0.0f;

    // Nn = 100000 = 8 * 12500 -> every group of 8 fully valid
    for (int n0 = blockIdx.x * 8; n0 < Nn; n0 += gridDim.x * 8) {
        #pragma unroll
        for (int q = 0; q < 4; q++)
            sa[half + 2 * q][j] = g_agg[(n0 + 2 * q + half) * 64 + j];
        __syncthreads();
        ull a0 = 0ull, a1 = 0ull, a2 = 0ull, a3 = 0ull;
        const ulonglong2* A0 = (const ulonglong2*)sa[half + 0];
        const ulonglong2* A1 = (const ulonglong2*)sa[half + 2];
        const ulonglong2* A2 = (const ulonglong2*)sa[half + 4];
        const ulonglong2* A3 = (const ulonglong2*)sa[half + 6];
        #pragma unroll
        for (int i2 = 0; i2 < 16; i2++) {
            ulonglong2 u0 = A0[i2], u1 = A1[i2], u2 = A2[i2], u3 = A3[i2];
            ull wx = w1[2 * i2], wy = w1[2 * i2 + 1];
            a0 = fma2(u0.x, wx, a0); a1 = fma2(u1.x, wx, a1);
            a2 = fma2(u2.x, wx, a2); a3 = fma2(u3.x, wx, a3);
            a0 = fma2(u0.y, wy, a0); a1 = fma2(u1.y, wy, a1);
            a2 = fma2(u2.y, wy, a2); a3 = fma2(u3.y, wy, a3);
        }
        {
            float2 f0 = up2(a0), f1 = up2(a1), f2 = up2(a2), f3 = up2(a3);
            st[half + 0][j] = sp(f0.x + f0.y + b1);
            st[half + 2][j] = sp(f1.x + f1.y + b1);
            st[half + 4][j] = sp(f2.x + f2.y + b1);
            st[half + 6][j] = sp(f3.x + f3.y + b1);
        }
        __syncthreads();
        ull o0 = 0ull, o1 = 0ull, o2 = 0ull, o3 = 0ull;
        const ulonglong2* T0 = (const ulonglong2*)st[half + 0];
        const ulonglong2* T1 = (const ulonglong2*)st[half + 2];
        const ulonglong2* T2 = (const ulonglong2*)st[half + 4];
        const ulonglong2* T3 = (const ulonglong2*)st[half + 6];
        #pragma unroll
        for (int i2 = 0; i2 < 16; i2++) {
            ulonglong2 u0 = T0[i2], u1 = T1[i2], u2 = T2[i2], u3 = T3[i2];
            ull wx = w2[2 * i2], wy = w2[2 * i2 + 1];
            o0 = fma2(u0.x, wx, o0); o1 = fma2(u1.x, wx, o1);
            o2 = fma2(u2.x, wx, o2); o3 = fma2(u3.x, wx, o3);
            o0 = fma2(u0.y, wy, o0); o1 = fma2(u1.y, wy, o1);
            o2 = fma2(u2.y, wy, o2); o3 = fma2(u3.y, wy, o3);
        }
        {
            float2 f0 = up2(o0), f1 = up2(o1), f2 = up2(o2), f3 = up2(o3);
            float r0 = f0.x + f0.y + b2;
            float r1 = f1.x + f1.y + b2;
            float r2 = f2.x + f2.y + b2;
            float r3 = f3.x + f3.y + b2;
            #pragma unroll
            for (int q = 0; q < 4; q++) {
                float oq = (q == 0) ? r0 : (q == 1) ? r1 : (q == 2) ? r2 : r3;
                int n = n0 + 2 * q + half;
                float hn = g_h[n * 64 + j] + fmaf(oq, gm, bt);
                g_h[n * 64 + j] = hn;
                ms += hn;
            }
        }
    }
    if (do_mean) {
        sm[tid] = ms;
        __syncthreads();
        if (half == 0) atomicAdd(&g_mean[j], sm[j] + sm[j + 64]);
    }
}

// ---- final head ----
__global__ void final_kernel(const float* __restrict__ oW1, const float* __restrict__ ob1,
                             const float* __restrict__ og1, const float* __restrict__ obt1,
                             const float* __restrict__ oW2, const float* __restrict__ ob2,
                             const float* __restrict__ og2, const float* __restrict__ obt2,
                             const float* __restrict__ fiW, const float* __restrict__ fib,
                             float* __restrict__ out) {
    __shared__ float gv[64], s1[32], s2[32];
    int t = threadIdx.x;  // 64 threads
    gv[t] = g_mean[t] * (1.0f / (float)Nn);
    __syncthreads();
    if (t < 32) {
        float acc = ob1[t];
        #pragma unroll
        for (int i = 0; i < 64; i++) acc = fmaf(gv[i], oW1[i * 32 + t], acc);
        s1[t] = fmaf(sp(acc) * INVBN, og1[t], obt1[t]);
    }
    __syncthreads();
    if (t < 32) {
        float acc = ob2[t];
        #pragma unroll
        for (int i = 0; i < 32; i++) acc = fmaf(s1[i], oW2[i * 32 + t], acc);
        s2[t] = fmaf(sp(acc) * INVBN, og2[t], obt2[t]);
    }
    __syncthreads();
    if (t < 3) {
        float acc = fib[t];
        #pragma unroll
        for (int i = 0; i < 32; i++) acc = fmaf(s2[i], fiW[i * 3 + t], acc);
        out[t] = acc;
    }
}

extern "C" void kernel_launch(void* const* d_in, const int* in_sizes, int n_in,
                              void* d_out, int out_size) {
    const float* x    = (const float*)d_in[0];
    const int*   eidx = (const int*)  d_in[1];
    const float* dist = (const float*)d_in[2];
    const float* embW = (const float*)d_in[4];
    const float* embB = (const float*)d_in[5];
    const float* fW1  = (const float*)d_in[6];
    const float* fb1  = (const float*)d_in[7];
    const float* fW2  = (const float*)d_in[8];
    const float* fb2  = (const float*)d_in[9];
    const float* iW1  = (const float*)d_in[10];
    const float* ib1  = (const float*)d_in[11];
    const float* iW2  = (const float*)d_in[12];
    const float* ib2  = (const float*)d_in[13];
    const float* gam  = (const float*)d_in[14];
    const float* bet  = (const float*)d_in[15];
    const float* oW1  = (const float*)d_in[16];
    const float* ob1  = (const float*)d_in[17];
    const float* og1  = (const float*)d_in[18];
    const float* obt1 = (const float*)d_in[19];
    const float* oW2  = (const float*)d_in[20];
    const float* ob2  = (const float*)d_in[21];
    const float* og2  = (const float*)d_in[22];
    const float* obt2 = (const float*)d_in[23];
    const float* fiW  = (const float*)d_in[24];
    const float* fib  = (const float*)d_in[25];
    float* out = (float*)d_out;

    table_kernel<<<(Ll * Kt) / 256, 256>>>(fW1, fb1, fW2, fb2);
    embed_kernel<<<(Nn * 16 + 255) / 256, 256>>>(x, embW, embB);
    hist_kernel<<<(Ee + 255) / 256, 256>>>(eidx);
    scan_kernel<<<NB1, 1024>>>();
    fill_kernel<<<(Ee + 255) / 256, 256>>>(eidx, dist);

    for (int l = 0; l < Ll; l++) {
        agg_kernel<<<(Nn * 32 + 255) / 256, 256>>>(l);
        node_kernel<<<444, 128>>>(iW1 + l * 4096, ib1 + l * 64,
                                  iW2 + l * 4096, ib2 + l * 64,
                                  gam + l * 64, bet + l * 64,
                                  (l == Ll - 1) ? 1 : 0);
    }

    final_kernel<<<1, 64>>>(oW1, ob1, og1, obt1, oW2, ob2, og2, obt2,
                            fiW, fib, out);
}

// round 13
// speedup vs baseline: 1.5522x; 1.5522x over previous
#include <cuda_runtime.h>
#include <cuda_bf16.h>
#include <math.h>

#define Nn 100000
#define Ee 1600000
#define Hh 64
#define Ll 3
#define Kt 8192
#define CUT 5.0f
#define INVBN 0.9995003747f   // 1/sqrt(1+1e-3)
#define NB1 98                // ceil(Nn/1024) scan blocks
#define NTILE 6250            // Nn/16 node tiles

typedef unsigned long long ull;
typedef unsigned int u32;

// ---- static device scratch ----
__device__ __align__(256) float g_h[Nn * Hh];       // node features, 25.6 MB
__device__ __align__(256) float g_agg[Nn * Hh];     // aggregation target, 25.6 MB
__device__ __align__(256) int4  g_ep4[Ee];          // (col, fs0, fs1, fs2), 25.6 MB
__device__ int   g_cnt[Nn];
__device__ int   g_off[Nn];
__device__ int   g_cur[Nn];
__device__ ull   g_state[NB1];                      // lookback scan states
__device__ float g_table[Ll * Kt];
__device__ float g_mean[Hh];

__device__ __forceinline__ float sp(float x) {      // softplus, stable
    return fmaxf(x, 0.0f) + log1pf(expf(-fabsf(x)));
}

// pack two f32 -> bf16x2 (lo at even col = low half, hi at odd col = high half)
__device__ __forceinline__ u32 packbf(float lo, float hi) {
    u32 r;
    asm("cvt.rn.bf16x2.f32 %0, %1, %2;" : "=r"(r) : "f"(hi), "f"(lo));
    return r;
}
__device__ __forceinline__ u32 smaddr(const void* p) {
    return (u32)__cvta_generic_to_shared(p);
}
__device__ __forceinline__ void ldsm4(u32* f, u32 addr) {
    asm volatile("ldmatrix.sync.aligned.m8n8.x4.shared.b16 {%0,%1,%2,%3},[%4];"
                 : "=r"(f[0]), "=r"(f[1]), "=r"(f[2]), "=r"(f[3]) : "r"(addr));
}
__device__ __forceinline__ void ldsm2t(u32& b0, u32& b1, u32 addr) {
    asm volatile("ldmatrix.sync.aligned.m8n8.x2.trans.shared.b16 {%0,%1},[%2];"
                 : "=r"(b0), "=r"(b1) : "r"(addr));
}
__device__ __forceinline__ void mma16816(float& d0, float& d1, float& d2, float& d3,
                                         const u32* a, u32 b0, u32 b1) {
    asm volatile("mma.sync.aligned.m16n8k16.row.col.f32.bf16.bf16.f32 "
                 "{%0,%1,%2,%3},{%4,%5,%6,%7},{%8,%9},{%0,%1,%2,%3};"
                 : "+f"(d0), "+f"(d1), "+f"(d2), "+f"(d3)
                 : "r"(a[0]), "r"(a[1]), "r"(a[2]), "r"(a[3]), "r"(b0), "r"(b1));
}

// ---- table: fs(d)*cut(d); fW2 rowsums computed per-block in smem ----
__global__ void table_kernel(const float* __restrict__ fW1,
                             const float* __restrict__ fb1,
                             const float* __restrict__ fW2,
                             const float* __restrict__ fb2) {
    int t = blockIdx.x * 256 + threadIdx.x;       // grid 96x256 == Ll*Kt
    int l = t >> 13;                              // same l for whole block
    __shared__ float sw2[64];
    __shared__ float sb2;
    if (threadIdx.x < 64) {
        const float* p = fW2 + l * Hh * Hh + threadIdx.x * Hh;
        float s = 0.0f;
        #pragma unroll
        for (int k = 0; k < Hh; k++) s += p[k];
        sw2[threadIdx.x] = s;
    }
    if (threadIdx.x == 64) {
        float s = 0.0f;
        for (int k = 0; k < Hh; k++) s += fb2[l * Hh + k];
        sb2 = s;
    }
    __syncthreads();
    int k = t & (Kt - 1);
    float d = k * (CUT / (float)(Kt - 1));
    float s = d * (2.0f / CUT) - 1.0f;
    const float* w1 = fW1 + l * Hh;
    const float* b1 = fb1 + l * Hh;
    float acc = sb2;
    #pragma unroll 8
    for (int j = 0; j < Hh; j++)
        acc = fmaf(tanhf(fmaf(s, w1[j], b1[j])), sw2[j], acc);
    float cut = 0.5f * (cosf(d * (float)(M_PI / 5.0)) + 1.0f);
    g_table[t] = acc * cut;
}

// ---- embedding: h = x @ emb_W + emb_b ; also zero cnt/mean/scan-state ----
__global__ void embed_kernel(const float* __restrict__ x,
                             const float* __restrict__ W,
                             const float* __restrict__ b) {
    __shared__ float sW[16 * 64];
    __shared__ float sb[64];
    int tid = threadIdx.x;
    for (int i = tid; i < 16 * 64; i += 256) sW[i] = W[i];
    if (tid < 64) sb[tid] = b[tid];
    __syncthreads();
    int t = blockIdx.x * 256 + tid;
    if (t < Nn) g_cnt[t] = 0;
    if (t < Hh) g_mean[t] = 0.0f;
    if (t < NB1) g_state[t] = 0ull;
    if (t >= Nn * 16) return;
    int n = t >> 4, q = t & 15, j0 = q * 4;
    const float* xr = x + n * 16;
    float4 acc = make_float4(sb[j0], sb[j0 + 1], sb[j0 + 2], sb[j0 + 3]);
    #pragma unroll
    for (int i = 0; i < 16; i++) {
        float xi = xr[i];
        acc.x = fmaf(xi, sW[i * 64 + j0 + 0], acc.x);
        acc.y = fmaf(xi, sW[i * 64 + j0 + 1], acc.y);
        acc.z = fmaf(xi, sW[i * 64 + j0 + 2], acc.z);
        acc.w = fmaf(xi, sW[i * 64 + j0 + 3], acc.w);
    }
    ((float4*)g_h)[t] = acc;
}

__global__ void hist_kernel(const int* __restrict__ eidx) {
    int e = blockIdx.x * blockDim.x + threadIdx.x;
    if (e < Ee) atomicAdd(&g_cnt[eidx[e]], 1);
}

// ---- single-pass decoupled-lookback exclusive scan of g_cnt -> g_off/g_cur ----
__global__ void __launch_bounds__(1024) scan_kernel() {
    int bid = blockIdx.x;
    int i = bid * 1024 + threadIdx.x;
    int v = (i < Nn) ? g_cnt[i] : 0;
    int lane = threadIdx.x & 31, w = threadIdx.x >> 5;
    int x = v;
    #pragma unroll
    for (int off = 1; off < 32; off <<= 1) {
        int y = __shfl_up_sync(0xffffffff, x, off);
        if (lane >= off) x += y;
    }
    __shared__ int wsum[32], wpre[32];
    __shared__ int stotal, sprefix;
    if (lane == 31) wsum[w] = x;
    __syncthreads();
    if (threadIdx.x < 32) {
        int s = wsum[threadIdx.x];
        int xs = s;
        #pragma unroll
        for (int off = 1; off < 32; off <<= 1) {
            int y = __shfl_up_sync(0xffffffff, xs, off);
            if ((int)threadIdx.x >= off) xs += y;
        }
        wpre[threadIdx.x] = xs - s;
        if (threadIdx.x == 31) stotal = xs;
    }
    __syncthreads();
    int total = stotal;
    if (threadIdx.x == 0) {
        if (bid == 0) {
            sprefix = 0;
            atomicExch(&g_state[0], (2ull << 32) | (unsigned)total);
        } else {
            atomicExch(&g_state[bid], (1ull << 32) | (unsigned)total);
            ull run = 0;
            int p = bid - 1;
            while (true) {
                ull sv = atomicAdd(&g_state[p], 0ull);
                unsigned st = (unsigned)(sv >> 32);
                if (st == 0u) { __nanosleep(32); continue; }
                run += (unsigned)sv;
                if (st == 2u) break;
                p--;
            }
            sprefix = (int)run;
            atomicExch(&g_state[bid], (2ull << 32) | (unsigned)(run + total));
        }
    }
    __syncthreads();
    if (i < Nn) {
        int o = x - v + wpre[w] + sprefix;
        g_off[i] = o;
        g_cur[i] = o;
    }
}

// scatter edges into CSR order; one int4 record (col, fs0, fs1, fs2)
__global__ void fill_kernel(const int* __restrict__ eidx,
                            const float* __restrict__ dist) {
    int e = blockIdx.x * blockDim.x + threadIdx.x;
    if (e >= Ee) return;
    int r = eidx[e];
    int c = eidx[Ee + e];
    float d = __ldg(dist + e);
    float u = d * ((float)(Kt - 1) / CUT);
    u = fminf(fmaxf(u, 0.0f), (float)(Kt - 2) + 0.999f);
    int i = (int)u;
    float fr = u - (float)i;
    float fs[Ll];
    #pragma unroll
    for (int l = 0; l < Ll; l++) {
        const float* tb = g_table + l * Kt;
        float t0 = __ldg(tb + i), t1 = __ldg(tb + i + 1);
        fs[l] = fmaf(fr, t1 - t0, t0);
    }
    int pos = atomicAdd(&g_cur[r], 1);
    g_ep4[pos] = make_int4(c, __float_as_int(fs[0]),
                           __float_as_int(fs[1]), __float_as_int(fs[2]));
}

// ============ per-layer edge aggregation: warp per row (R10 proven form) =======
__global__ void __launch_bounds__(256) agg_kernel(int l) {
    int gw = (blockIdx.x * 256 + threadIdx.x) >> 5;
    if (gw >= Nn) return;
    int lane = threadIdx.x & 31;
    int beg = g_off[gw], deg = g_cnt[gw];
    float2 acc = make_float2(0.0f, 0.0f);
    const float2* hb = (const float2*)g_h;
    for (int base = 0; base < deg; base += 32) {
        int rem = deg - base;
        if (rem > 32) rem = 32;
        int col_r = 0, fs_r = 0;
        if (lane < rem) {
            int4 m = __ldg(&g_ep4[beg + base + lane]);
            col_r = m.x;
            fs_r = (l == 0) ? m.y : (l == 1 ? m.z : m.w);
        }
        int d = 0;
        #pragma unroll 4
        for (; d + 4 <= rem; d += 4) {
            int c0 = __shfl_sync(0xffffffff, col_r, d + 0);
            int c1 = __shfl_sync(0xffffffff, col_r, d + 1);
            int c2 = __shfl_sync(0xffffffff, col_r, d + 2);
            int c3 = __shfl_sync(0xffffffff, col_r, d + 3);
            float f0 = __int_as_float(__shfl_sync(0xffffffff, fs_r, d + 0));
            float f1 = __int_as_float(__shfl_sync(0xffffffff, fs_r, d + 1));
            float f2 = __int_as_float(__shfl_sync(0xffffffff, fs_r, d + 2));
            float f3 = __int_as_float(__shfl_sync(0xffffffff, fs_r, d + 3));
            float2 v0 = __ldg(hb + c0 * 32 + lane);
            float2 v1 = __ldg(hb + c1 * 32 + lane);
            float2 v2 = __ldg(hb + c2 * 32 + lane);
            float2 v3 = __ldg(hb + c3 * 32 + lane);
            acc.x = fmaf(v0.x, f0, acc.x);
            acc.y = fmaf(v0.y, f0, acc.y);
            acc.x = fmaf(v1.x, f1, acc.x);
            acc.y = fmaf(v1.y, f1, acc.y);
            acc.x = fmaf(v2.x, f2, acc.x);
            acc.y = fmaf(v2.y, f2, acc.y);
            acc.x = fmaf(v3.x, f3, acc.x);
            acc.y = fmaf(v3.y, f3, acc.y);
        }
        for (; d < rem; d++) {
            int c0 = __shfl_sync(0xffffffff, col_r, d);
            float f0 = __int_as_float(__shfl_sync(0xffffffff, fs_r, d));
            float2 v0 = __ldg(hb + c0 * 32 + lane);
            acc.x = fmaf(v0.x, f0, acc.x);
            acc.y = fmaf(v0.y, f0, acc.y);
        }
    }
    ((float2*)g_agg)[gw * 32 + lane] = acc;
}

// ===== node MLP via tensor cores: warp = 16 nodes, bf16 mma, split weights ====
// smem: W1/W2 hi+lo bf16 [64 x 72] (stride 144B, conflict-free, 16B aligned),
// per-warp A/T tile [16 x 72] bf16 (As reused as Ts). Static smem ~47.4 KB.
__global__ void __launch_bounds__(128) node_mma_kernel(
    const float* __restrict__ iW1, const float* __restrict__ ib1,
    const float* __restrict__ iW2, const float* __restrict__ ib2,
    const float* __restrict__ gam, const float* __restrict__ bet,
    int do_mean) {
    __shared__ __align__(16) __nv_bfloat16 W1h[64 * 72], W1l[64 * 72];
    __shared__ __align__(16) __nv_bfloat16 W2h[64 * 72], W2l[64 * 72];
    __shared__ __align__(16) u32 AT[4][16 * 36];     // per-warp bf16 tile
    __shared__ float sb1[64], sb2[64], sgm[64], sbt[64], smean[64];
    int tid = threadIdx.x, wid = tid >> 5, lane = tid & 31;
    for (int idx = tid; idx < 4096; idx += 128) {
        int i = idx >> 6, j = idx & 63;
        float w = iW1[idx];
        __nv_bfloat16 hi = __float2bfloat16_rn(w);
        W1h[i * 72 + j] = hi;
        W1l[i * 72 + j] = __float2bfloat16_rn(w - __bfloat162float(hi));
        w = iW2[idx];
        hi = __float2bfloat16_rn(w);
        W2h[i * 72 + j] = hi;
        W2l[i * 72 + j] = __float2bfloat16_rn(w - __bfloat162float(hi));
    }
    if (tid < 64) {
        sb1[tid] = ib1[tid]; sb2[tid] = ib2[tid];
        sgm[tid] = gam[tid] * INVBN; sbt[tid] = bet[tid];
        smean[tid] = 0.0f;
    }
    __syncthreads();

    u32 at_base = smaddr(&AT[wid][0]);
    u32 w1h_b = smaddr(W1h), w1l_b = smaddr(W1l);
    u32 w2h_b = smaddr(W2h), w2l_b = smaddr(W2l);
    int tid4 = lane & 3, gid = lane >> 2;
    u32 arow = at_base + (lane & 15) * 144 + ((lane >> 4) & 1) * 16;
    u32 brow_off = (lane & 15) * 144;   // k-row per lane for B ldmatrix

    float ms[16];
    #pragma unroll
    for (int k = 0; k < 16; k++) ms[k] = 0.0f;

    for (int tile = blockIdx.x * 4 + wid; tile < NTILE; tile += gridDim.x * 4) {
        int n0 = tile << 4;
        __syncwarp();
        // stage agg tile -> bf16
        #pragma unroll
        for (int q = lane; q < 256; q += 32) {
            int row = q >> 4, cq = q & 15;
            float4 v = __ldg((const float4*)(g_agg + (n0 + row) * 64 + cq * 4));
            AT[wid][row * 36 + cq * 2 + 0] = packbf(v.x, v.y);
            AT[wid][row * 36 + cq * 2 + 1] = packbf(v.z, v.w);
        }
        __syncwarp();
        u32 a[4][4];
        #pragma unroll
        for (int kk = 0; kk < 4; kk++) ldsm4(a[kk], arow + kk * 32);
        __syncwarp();   // A frags in regs; AT buffer now reusable as Ts
        // GEMM1 + softplus -> Ts
        #pragma unroll
        for (int nn = 0; nn < 8; nn++) {
            float d0 = 0.f, d1 = 0.f, d2 = 0.f, d3 = 0.f;
            #pragma unroll
            for (int kk = 0; kk < 4; kk++) {
                u32 b0, b1;
                u32 ko = kk * 16 * 144 + brow_off + nn * 16;
                ldsm2t(b0, b1, w1h_b + ko);
                mma16816(d0, d1, d2, d3, a[kk], b0, b1);
                ldsm2t(b0, b1, w1l_b + ko);
                mma16816(d0, d1, d2, d3, a[kk], b0, b1);
            }
            int c0 = nn * 8 + tid4 * 2;
            float s0 = sp(d0 + sb1[c0]), s1 = sp(d1 + sb1[c0 + 1]);
            float s2 = sp(d2 + sb1[c0]), s3 = sp(d3 + sb1[c0 + 1]);
            AT[wid][gid * 36 + nn * 4 + tid4] = packbf(s0, s1);
            AT[wid][(gid + 8) * 36 + nn * 4 + tid4] = packbf(s2, s3);
        }
        __syncwarp();
        #pragma unroll
        for (int kk = 0; kk < 4; kk++) ldsm4(a[kk], arow + kk * 32);
        // GEMM2 + BN/residual epilogue
        #pragma unroll
        for (int nn = 0; nn < 8; nn++) {
            float d0 = 0.f, d1 = 0.f, d2 = 0.f, d3 = 0.f;
            #pragma unroll
            for (int kk = 0; kk < 4; kk++) {
                u32 b0, b1;
                u32 ko = kk * 16 * 144 + brow_off + nn * 16;
                ldsm2t(b0, b1, w2h_b + ko);
                mma16816(d0, d1, d2, d3, a[kk], b0, b1);
                ldsm2t(b0, b1, w2l_b + ko);
                mma16816(d0, d1, d2, d3, a[kk], b0, b1);
            }
            int c0 = nn * 8 + tid4 * 2;
            float2* hp0 = (float2*)(g_h + (n0 + gid) * 64 + c0);
            float2* hp1 = (float2*)(g_h + (n0 + gid + 8) * 64 + c0);
            float2 h0 = *hp0, h1 = *hp1;
            h0.x += fmaf(d0 + sb2[c0],     sgm[c0],     sbt[c0]);
            h0.y += fmaf(d1 + sb2[c0 + 1], sgm[c0 + 1], sbt[c0 + 1]);
            h1.x += fmaf(d2 + sb2[c0],     sgm[c0],     sbt[c0]);
            h1.y += fmaf(d3 + sb2[c0 + 1], sgm[c0 + 1], sbt[c0 + 1]);
            *hp0 = h0; *hp1 = h1;
            ms[nn * 2 + 0] += h0.x + h1.x;
            ms[nn * 2 + 1] += h0.y + h1.y;
        }
    }
    if (do_mean) {
        #pragma unroll
        for (int k = 0; k < 16; k++) {
            ms[k] += __shfl_xor_sync(0xffffffff, ms[k], 4);
            ms[k] += __shfl_xor_sync(0xffffffff, ms[k], 8);
            ms[k] += __shfl_xor_sync(0xffffffff, ms[k], 16);
        }
        if (lane < 4) {
            #pragma unroll
            for (int nn = 0; nn < 8; nn++) {
                atomicAdd(&smean[nn * 8 + lane * 2 + 0], ms[nn * 2 + 0]);
                atomicAdd(&smean[nn * 8 + lane * 2 + 1], ms[nn * 2 + 1]);
            }
        }
        __syncthreads();
        if (tid < 64) atomicAdd(&g_mean[tid], smean[tid]);
    }
}

// ---- final head ----
__global__ void final_kernel(const float* __restrict__ oW1, const float* __restrict__ ob1,
                             const float* __restrict__ og1, const float* __restrict__ obt1,
                             const float* __restrict__ oW2, const float* __restrict__ ob2,
                             const float* __restrict__ og2, const float* __restrict__ obt2,
                             const float* __restrict__ fiW, const float* __restrict__ fib,
                             float* __restrict__ out) {
    __shared__ float gv[64], s1[32], s2[32];
    int t = threadIdx.x;  // 64 threads
    gv[t] = g_mean[t] * (1.0f / (float)Nn);
    __syncthreads();
    if (t < 32) {
        float acc = ob1[t];
        #pragma unroll
        for (int i = 0; i < 64; i++) acc = fmaf(gv[i], oW1[i * 32 + t], acc);
        s1[t] = fmaf(sp(acc) * INVBN, og1[t], obt1[t]);
    }
    __syncthreads();
    if (t < 32) {
        float acc = ob2[t];
        #pragma unroll
        for (int i = 0; i < 32; i++) acc = fmaf(s1[i], oW2[i * 32 + t], acc);
        s2[t] = fmaf(sp(acc) * INVBN, og2[t], obt2[t]);
    }
    __syncthreads();
    if (t < 3) {
        float acc = fib[t];
        #pragma unroll
        for (int i = 0; i < 32; i++) acc = fmaf(s2[i], fiW[i * 3 + t], acc);
        out[t] = acc;
    }
}

extern "C" void kernel_launch(void* const* d_in, const int* in_sizes, int n_in,
                              void* d_out, int out_size) {
    const float* x    = (const float*)d_in[0];
    const int*   eidx = (const int*)  d_in[1];
    const float* dist = (const float*)d_in[2];
    const float* embW = (const float*)d_in[4];
    const float* embB = (const float*)d_in[5];
    const float* fW1  = (const float*)d_in[6];
    const float* fb1  = (const float*)d_in[7];
    const float* fW2  = (const float*)d_in[8];
    const float* fb2  = (const float*)d_in[9];
    const float* iW1  = (const float*)d_in[10];
    const float* ib1  = (const float*)d_in[11];
    const float* iW2  = (const float*)d_in[12];
    const float* ib2  = (const float*)d_in[13];
    const float* gam  = (const float*)d_in[14];
    const float* bet  = (const float*)d_in[15];
    const float* oW1  = (const float*)d_in[16];
    const float* ob1  = (const float*)d_in[17];
    const float* og1  = (const float*)d_in[18];
    const float* obt1 = (const float*)d_in[19];
    const float* oW2  = (const float*)d_in[20];
    const float* ob2  = (const float*)d_in[21];
    const float* og2  = (const float*)d_in[22];
    const float* obt2 = (const float*)d_in[23];
    const float* fiW  = (const float*)d_in[24];
    const float* fib  = (const float*)d_in[25];
    float* out = (float*)d_out;

    table_kernel<<<(Ll * Kt) / 256, 256>>>(fW1, fb1, fW2, fb2);
    embed_kernel<<<(Nn * 16 + 255) / 256, 256>>>(x, embW, embB);
    hist_kernel<<<(Ee + 255) / 256, 256>>>(eidx);
    scan_kernel<<<NB1, 1024>>>();
    fill_kernel<<<(Ee + 255) / 256, 256>>>(eidx, dist);

    for (int l = 0; l < Ll; l++) {
        agg_kernel<<<(Nn * 32 + 255) / 256, 256>>>(l);
        node_mma_kernel<<<444, 128>>>(iW1 + l * 4096, ib1 + l * 64,
                                      iW2 + l * 4096, ib2 + l * 64,
                                      gam + l * 64, bet + l * 64,
                                      (l == Ll - 1) ? 1 : 0);
    }

    final_kernel<<<1, 64>>>(oW1, ob1, og1, obt1, oW2, ob2, og2, obt2,
                            fiW, fib, out);
}

// round 14
// speedup vs baseline: 1.5565x; 1.0028x over previous
#include <cuda_runtime.h>
#include <cuda_bf16.h>
#include <math.h>

#define Nn 100000
#define Ee 1600000
#define Hh 64
#define Ll 3
#define Kt 8192
#define CUT 5.0f
#define INVBN 0.9995003747f   // 1/sqrt(1+1e-3)
#define NB1 98                // ceil(Nn/1024) scan blocks
#define NTILE 6250            // Nn/16 node tiles

typedef unsigned long long ull;
typedef unsigned int u32;

// ---- static device scratch ----
__device__ __align__(256) float g_h[Nn * Hh];       // node features fp32, 25.6 MB
__device__ __align__(256) u32   g_hb[Nn * 32];      // bf16x2 gather mirror, 12.8 MB
__device__ __align__(256) u32   g_aggb[Nn * 32];    // bf16x2 agg result, 12.8 MB
__device__ __align__(256) int4  g_ep4[Ee];          // (col, fs0, fs1, fs2), 25.6 MB
__device__ int   g_cnt[Nn];
__device__ int   g_off[Nn];
__device__ int   g_cur[Nn];
__device__ ull   g_state[NB1];                      // lookback scan states
__device__ float g_table[Ll * Kt];
__device__ float g_mean[Hh];

__device__ __forceinline__ float sp(float x) {      // softplus, stable
    return fmaxf(x, 0.0f) + log1pf(expf(-fabsf(x)));
}

// pack two f32 -> bf16x2 (lo in low 16 bits, hi in high 16 bits)
__device__ __forceinline__ u32 packbf(float lo, float hi) {
    u32 r;
    asm("cvt.rn.bf16x2.f32 %0, %1, %2;" : "=r"(r) : "f"(hi), "f"(lo));
    return r;
}
// unpack bf16x2 -> two f32 via pure ALU bit ops (NO F2F converts)
__device__ __forceinline__ float bflo(u32 r) { return __uint_as_float(r << 16); }
__device__ __forceinline__ float bfhi(u32 r) { return __uint_as_float(r & 0xffff0000u); }

__device__ __forceinline__ u32 smaddr(const void* p) {
    return (u32)__cvta_generic_to_shared(p);
}
__device__ __forceinline__ void ldsm4(u32* f, u32 addr) {
    asm volatile("ldmatrix.sync.aligned.m8n8.x4.shared.b16 {%0,%1,%2,%3},[%4];"
                 : "=r"(f[0]), "=r"(f[1]), "=r"(f[2]), "=r"(f[3]) : "r"(addr));
}
__device__ __forceinline__ void ldsm2t(u32& b0, u32& b1, u32 addr) {
    asm volatile("ldmatrix.sync.aligned.m8n8.x2.trans.shared.b16 {%0,%1},[%2];"
                 : "=r"(b0), "=r"(b1) : "r"(addr));
}
__device__ __forceinline__ void mma16816(float& d0, float& d1, float& d2, float& d3,
                                         const u32* a, u32 b0, u32 b1) {
    asm volatile("mma.sync.aligned.m16n8k16.row.col.f32.bf16.bf16.f32 "
                 "{%0,%1,%2,%3},{%4,%5,%6,%7},{%8,%9},{%0,%1,%2,%3};"
                 : "+f"(d0), "+f"(d1), "+f"(d2), "+f"(d3)
                 : "r"(a[0]), "r"(a[1]), "r"(a[2]), "r"(a[3]), "r"(b0), "r"(b1));
}

// ---- table: fs(d)*cut(d); fW2 rowsums computed per-block in smem ----
__global__ void table_kernel(const float* __restrict__ fW1,
                             const float* __restrict__ fb1,
                             const float* __restrict__ fW2,
                             const float* __restrict__ fb2) {
    int t = blockIdx.x * 256 + threadIdx.x;       // grid 96x256 == Ll*Kt
    int l = t >> 13;                              // same l for whole block
    __shared__ float sw2[64];
    __shared__ float sb2;
    if (threadIdx.x < 64) {
        const float* p = fW2 + l * Hh * Hh + threadIdx.x * Hh;
        float s = 0.0f;
        #pragma unroll
        for (int k = 0; k < Hh; k++) s += p[k];
        sw2[threadIdx.x] = s;
    }
    if (threadIdx.x == 64) {
        float s = 0.0f;
        for (int k = 0; k < Hh; k++) s += fb2[l * Hh + k];
        sb2 = s;
    }
    __syncthreads();
    int k = t & (Kt - 1);
    float d = k * (CUT / (float)(Kt - 1));
    float s = d * (2.0f / CUT) - 1.0f;
    const float* w1 = fW1 + l * Hh;
    const float* b1 = fb1 + l * Hh;
    float acc = sb2;
    #pragma unroll 8
    for (int j = 0; j < Hh; j++)
        acc = fmaf(tanhf(fmaf(s, w1[j], b1[j])), sw2[j], acc);
    float cut = 0.5f * (cosf(d * (float)(M_PI / 5.0)) + 1.0f);
    g_table[t] = acc * cut;
}

// ---- embedding: h = x @ emb_W + emb_b ; bf16 mirror; zero cnt/mean/state ----
__global__ void embed_kernel(const float* __restrict__ x,
                             const float* __restrict__ W,
                             const float* __restrict__ b) {
    __shared__ float sW[16 * 64];
    __shared__ float sb[64];
    int tid = threadIdx.x;
    for (int i = tid; i < 16 * 64; i += 256) sW[i] = W[i];
    if (tid < 64) sb[tid] = b[tid];
    __syncthreads();
    int t = blockIdx.x * 256 + tid;
    if (t < Nn) g_cnt[t] = 0;
    if (t < Hh) g_mean[t] = 0.0f;
    if (t < NB1) g_state[t] = 0ull;
    if (t >= Nn * 16) return;
    int n = t >> 4, q = t & 15, j0 = q * 4;
    const float* xr = x + n * 16;
    float4 acc = make_float4(sb[j0], sb[j0 + 1], sb[j0 + 2], sb[j0 + 3]);
    #pragma unroll
    for (int i = 0; i < 16; i++) {
        float xi = xr[i];
        acc.x = fmaf(xi, sW[i * 64 + j0 + 0], acc.x);
        acc.y = fmaf(xi, sW[i * 64 + j0 + 1], acc.y);
        acc.z = fmaf(xi, sW[i * 64 + j0 + 2], acc.z);
        acc.w = fmaf(xi, sW[i * 64 + j0 + 3], acc.w);
    }
    ((float4*)g_h)[t] = acc;
    g_hb[n * 32 + q * 2 + 0] = packbf(acc.x, acc.y);
    g_hb[n * 32 + q * 2 + 1] = packbf(acc.z, acc.w);
}

__global__ void hist_kernel(const int* __restrict__ eidx) {
    int e = blockIdx.x * blockDim.x + threadIdx.x;
    if (e < Ee) atomicAdd(&g_cnt[eidx[e]], 1);
}

// ---- single-pass decoupled-lookback exclusive scan of g_cnt -> g_off/g_cur ----
__global__ void __launch_bounds__(1024) scan_kernel() {
    int bid = blockIdx.x;
    int i = bid * 1024 + threadIdx.x;
    int v = (i < Nn) ? g_cnt[i] : 0;
    int lane = threadIdx.x & 31, w = threadIdx.x >> 5;
    int x = v;
    #pragma unroll
    for (int off = 1; off < 32; off <<= 1) {
        int y = __shfl_up_sync(0xffffffff, x, off);
        if (lane >= off) x += y;
    }
    __shared__ int wsum[32], wpre[32];
    __shared__ int stotal, sprefix;
    if (lane == 31) wsum[w] = x;
    __syncthreads();
    if (threadIdx.x < 32) {
        int s = wsum[threadIdx.x];
        int xs = s;
        #pragma unroll
        for (int off = 1; off < 32; off <<= 1) {
            int y = __shfl_up_sync(0xffffffff, xs, off);
            if ((int)threadIdx.x >= off) xs += y;
        }
        wpre[threadIdx.x] = xs - s;
        if (threadIdx.x == 31) stotal = xs;
    }
    __syncthreads();
    int total = stotal;
    if (threadIdx.x == 0) {
        if (bid == 0) {
            sprefix = 0;
            atomicExch(&g_state[0], (2ull << 32) | (unsigned)total);
        } else {
            atomicExch(&g_state[bid], (1ull << 32) | (unsigned)total);
            ull run = 0;
            int p = bid - 1;
            while (true) {
                ull sv = atomicAdd(&g_state[p], 0ull);
                unsigned st = (unsigned)(sv >> 32);
                if (st == 0u) { __nanosleep(32); continue; }
                run += (unsigned)sv;
                if (st == 2u) break;
                p--;
            }
            sprefix = (int)run;
            atomicExch(&g_state[bid], (2ull << 32) | (unsigned)(run + total));
        }
    }
    __syncthreads();
    if (i < Nn) {
        int o = x - v + wpre[w] + sprefix;
        g_off[i] = o;
        g_cur[i] = o;
    }
}

// scatter edges into CSR order; one int4 record (col, fs0, fs1, fs2)
__global__ void fill_kernel(const int* __restrict__ eidx,
                            const float* __restrict__ dist) {
    int e = blockIdx.x * blockDim.x + threadIdx.x;
    if (e >= Ee) return;
    int r = eidx[e];
    int c = eidx[Ee + e];
    float d = __ldg(dist + e);
    float u = d * ((float)(Kt - 1) / CUT);
    u = fminf(fmaxf(u, 0.0f), (float)(Kt - 2) + 0.999f);
    int i = (int)u;
    float fr = u - (float)i;
    float fs[Ll];
    #pragma unroll
    for (int l = 0; l < Ll; l++) {
        const float* tb = g_table + l * Kt;
        float t0 = __ldg(tb + i), t1 = __ldg(tb + i + 1);
        fs[l] = fmaf(fr, t1 - t0, t0);
    }
    int pos = atomicAdd(&g_cur[r], 1);
    g_ep4[pos] = make_int4(c, __float_as_int(fs[0]),
                           __float_as_int(fs[1]), __float_as_int(fs[2]));
}

// ============ per-layer edge aggregation: warp per row, bf16 gather ============
// R10 skeleton; gather is one LDG.32 per lane (4 sectors/edge), unpack is pure
// ALU bit-ops (no F2F), fp32 accumulate, packed-bf16 output for the MMA stage.
__global__ void __launch_bounds__(256) agg_kernel(int l) {
    int gw = (blockIdx.x * 256 + threadIdx.x) >> 5;
    if (gw >= Nn) return;
    int lane = threadIdx.x & 31;
    int beg = g_off[gw], deg = g_cnt[gw];
    float2 acc = make_float2(0.0f, 0.0f);
    const u32* hb = g_hb;
    for (int base = 0; base < deg; base += 32) {
        int rem = deg - base;
        if (rem > 32) rem = 32;
        int col_r = 0, fs_r = 0;
        if (lane < rem) {
            int4 m = __ldg(&g_ep4[beg + base + lane]);
            col_r = m.x;
            fs_r = (l == 0) ? m.y : (l == 1 ? m.z : m.w);
        }
        int d = 0;
        #pragma unroll 4
        for (; d + 4 <= rem; d += 4) {
            int c0 = __shfl_sync(0xffffffff, col_r, d + 0);
            int c1 = __shfl_sync(0xffffffff, col_r, d + 1);
            int c2 = __shfl_sync(0xffffffff, col_r, d + 2);
            int c3 = __shfl_sync(0xffffffff, col_r, d + 3);
            float f0 = __int_as_float(__shfl_sync(0xffffffff, fs_r, d + 0));
            float f1 = __int_as_float(__shfl_sync(0xffffffff, fs_r, d + 1));
            float f2 = __int_as_float(__shfl_sync(0xffffffff, fs_r, d + 2));
            float f3 = __int_as_float(__shfl_sync(0xffffffff, fs_r, d + 3));
            u32 r0 = __ldg(hb + c0 * 32 + lane);
            u32 r1 = __ldg(hb + c1 * 32 + lane);
            u32 r2 = __ldg(hb + c2 * 32 + lane);
            u32 r3 = __ldg(hb + c3 * 32 + lane);
            acc.x = fmaf(bflo(r0), f0, acc.x);
            acc.y = fmaf(bfhi(r0), f0, acc.y);
            acc.x = fmaf(bflo(r1), f1, acc.x);
            acc.y = fmaf(bfhi(r1), f1, acc.y);
            acc.x = fmaf(bflo(r2), f2, acc.x);
            acc.y = fmaf(bfhi(r2), f2, acc.y);
            acc.x = fmaf(bflo(r3), f3, acc.x);
            acc.y = fmaf(bfhi(r3), f3, acc.y);
        }
        for (; d < rem; d++) {
            int c0 = __shfl_sync(0xffffffff, col_r, d);
            float f0 = __int_as_float(__shfl_sync(0xffffffff, fs_r, d));
            u32 r0 = __ldg(hb + c0 * 32 + lane);
            acc.x = fmaf(bflo(r0), f0, acc.x);
            acc.y = fmaf(bfhi(r0), f0, acc.y);
        }
    }
    g_aggb[gw * 32 + lane] = packbf(acc.x, acc.y);
}

// ===== node MLP via tensor cores: warp = 16 nodes, bf16 mma, split weights ====
__global__ void __launch_bounds__(128) node_mma_kernel(
    const float* __restrict__ iW1, const float* __restrict__ ib1,
    const float* __restrict__ iW2, const float* __restrict__ ib2,
    const float* __restrict__ gam, const float* __restrict__ bet,
    int flags) {   // bit0: mean; bit1: write bf16 mirror
    __shared__ __align__(16) __nv_bfloat16 W1h[64 * 72], W1l[64 * 72];
    __shared__ __align__(16) __nv_bfloat16 W2h[64 * 72], W2l[64 * 72];
    __shared__ __align__(16) u32 AT[4][16 * 36];     // per-warp bf16 tile
    __shared__ float sb1[64], sb2[64], sgm[64], sbt[64], smean[64];
    int tid = threadIdx.x, wid = tid >> 5, lane = tid & 31;
    int do_mean = flags & 1, do_mir = flags & 2;
    for (int idx = tid; idx < 4096; idx += 128) {
        int i = idx >> 6, j = idx & 63;
        float w = iW1[idx];
        __nv_bfloat16 hi = __float2bfloat16_rn(w);
        W1h[i * 72 + j] = hi;
        W1l[i * 72 + j] = __float2bfloat16_rn(w - __bfloat162float(hi));
        w = iW2[idx];
        hi = __float2bfloat16_rn(w);
        W2h[i * 72 + j] = hi;
        W2l[i * 72 + j] = __float2bfloat16_rn(w - __bfloat162float(hi));
    }
    if (tid < 64) {
        sb1[tid] = ib1[tid]; sb2[tid] = ib2[tid];
        sgm[tid] = gam[tid] * INVBN; sbt[tid] = bet[tid];
        smean[tid] = 0.0f;
    }
    __syncthreads();

    u32 at_base = smaddr(&AT[wid][0]);
    u32 w1h_b = smaddr(W1h), w1l_b = smaddr(W1l);
    u32 w2h_b = smaddr(W2h), w2l_b = smaddr(W2l);
    int tid4 = lane & 3, gid = lane >> 2;
    u32 arow = at_base + (lane & 15) * 144 + ((lane >> 4) & 1) * 16;
    u32 brow_off = (lane & 15) * 144;   // k-row per lane for B ldmatrix

    float ms[16];
    #pragma unroll
    for (int k = 0; k < 16; k++) ms[k] = 0.0f;

    for (int tile = blockIdx.x * 4 + wid; tile < NTILE; tile += gridDim.x * 4) {
        int n0 = tile << 4;
        __syncwarp();
        // stage agg tile (already packed bf16) -> smem
        #pragma unroll
        for (int q = lane; q < 512; q += 32) {
            int row = q >> 5, p = q & 31;
            AT[wid][row * 36 + p] = __ldg(g_aggb + (n0 + row) * 32 + p);
        }
        __syncwarp();
        u32 a[4][4];
        #pragma unroll
        for (int kk = 0; kk < 4; kk++) ldsm4(a[kk], arow + kk * 32);
        __syncwarp();   // A frags in regs; AT buffer now reusable as Ts
        // GEMM1 + softplus -> Ts
        #pragma unroll
        for (int nn = 0; nn < 8; nn++) {
            float d0 = 0.f, d1 = 0.f, d2 = 0.f, d3 = 0.f;
            #pragma unroll
            for (int kk = 0; kk < 4; kk++) {
                u32 b0, b1;
                u32 ko = kk * 16 * 144 + brow_off + nn * 16;
                ldsm2t(b0, b1, w1h_b + ko);
                mma16816(d0, d1, d2, d3, a[kk], b0, b1);
                ldsm2t(b0, b1, w1l_b + ko);
                mma16816(d0, d1, d2, d3, a[kk], b0, b1);
            }
            int c0 = nn * 8 + tid4 * 2;
            float s0 = sp(d0 + sb1[c0]), s1 = sp(d1 + sb1[c0 + 1]);
            float s2 = sp(d2 + sb1[c0]), s3 = sp(d3 + sb1[c0 + 1]);
            AT[wid][gid * 36 + nn * 4 + tid4] = packbf(s0, s1);
            AT[wid][(gid + 8) * 36 + nn * 4 + tid4] = packbf(s2, s3);
        }
        __syncwarp();
        #pragma unroll
        for (int kk = 0; kk < 4; kk++) ldsm4(a[kk], arow + kk * 32);
        // GEMM2 + BN/residual epilogue (+ bf16 mirror for next layer's gather)
        #pragma unroll
        for (int nn = 0; nn < 8; nn++) {
            float d0 = 0.f, d1 = 0.f, d2 = 0.f, d3 = 0.f;
            #pragma unroll
            for (int kk = 0; kk < 4; kk++) {
                u32 b0, b1;
                u32 ko = kk * 16 * 144 + brow_off + nn * 16;
                ldsm2t(b0, b1, w2h_b + ko);
                mma16816(d0, d1, d2, d3, a[kk], b0, b1);
                ldsm2t(b0, b1, w2l_b + ko);
                mma16816(d0, d1, d2, d3, a[kk], b0, b1);
            }
            int c0 = nn * 8 + tid4 * 2;
            float2* hp0 = (float2*)(g_h + (n0 + gid) * 64 + c0);
            float2* hp1 = (float2*)(g_h + (n0 + gid + 8) * 64 + c0);
            float2 h0 = *hp0, h1 = *hp1;
            h0.x += fmaf(d0 + sb2[c0],     sgm[c0],     sbt[c0]);
            h0.y += fmaf(d1 + sb2[c0 + 1], sgm[c0 + 1], sbt[c0 + 1]);
            h1.x += fmaf(d2 + sb2[c0],     sgm[c0],     sbt[c0]);
            h1.y += fmaf(d3 + sb2[c0 + 1], sgm[c0 + 1], sbt[c0 + 1]);
            *hp0 = h0; *hp1 = h1;
            if (do_mir) {
                g_hb[(n0 + gid) * 32 + (c0 >> 1)] = packbf(h0.x, h0.y);
                g_hb[(n0 + gid + 8) * 32 + (c0 >> 1)] = packbf(h1.x, h1.y);
            }
            ms[nn * 2 + 0] += h0.x + h1.x;
            ms[nn * 2 + 1] += h0.y + h1.y;
        }
    }
    if (do_mean) {
        #pragma unroll
        for (int k = 0; k < 16; k++) {
            ms[k] += __shfl_xor_sync(0xffffffff, ms[k], 4);
            ms[k] += __shfl_xor_sync(0xffffffff, ms[k], 8);
            ms[k] += __shfl_xor_sync(0xffffffff, ms[k], 16);
        }
        if (lane < 4) {
            #pragma unroll
            for (int nn = 0; nn < 8; nn++) {
                atomicAdd(&smean[nn * 8 + lane * 2 + 0], ms[nn * 2 + 0]);
                atomicAdd(&smean[nn * 8 + lane * 2 + 1], ms[nn * 2 + 1]);
            }
        }
        __syncthreads();
        if (tid < 64) atomicAdd(&g_mean[tid], smean[tid]);
    }
}

// ---- final head ----
__global__ void final_kernel(const float* __restrict__ oW1, const float* __restrict__ ob1,
                             const float* __restrict__ og1, const float* __restrict__ obt1,
                             const float* __restrict__ oW2, const float* __restrict__ ob2,
                             const float* __restrict__ og2, const float* __restrict__ obt2,
                             const float* __restrict__ fiW, const float* __restrict__ fib,
                             float* __restrict__ out) {
    __shared__ float gv[64], s1[32], s2[32];
    int t = threadIdx.x;  // 64 threads
    gv[t] = g_mean[t] * (1.0f / (float)Nn);
    __syncthreads();
    if (t < 32) {
        float acc = ob1[t];
        #pragma unroll
        for (int i = 0; i < 64; i++) acc = fmaf(gv[i], oW1[i * 32 + t], acc);
        s1[t] = fmaf(sp(acc) * INVBN, og1[t], obt1[t]);
    }
    __syncthreads();
    if (t < 32) {
        float acc = ob2[t];
        #pragma unroll
        for (int i = 0; i < 32; i++) acc = fmaf(s1[i], oW2[i * 32 + t], acc);
        s2[t] = fmaf(sp(acc) * INVBN, og2[t], obt2[t]);
    }
    __syncthreads();
    if (t < 3) {
        float acc = fib[t];
        #pragma unroll
        for (int i = 0; i < 32; i++) acc = fmaf(s2[i], fiW[i * 3 + t], acc);
        out[t] = acc;
    }
}

extern "C" void kernel_launch(void* const* d_in, const int* in_sizes, int n_in,
                              void* d_out, int out_size) {
    const float* x    = (const float*)d_in[0];
    const int*   eidx = (const int*)  d_in[1];
    const float* dist = (const float*)d_in[2];
    const float* embW = (const float*)d_in[4];
    const float* embB = (const float*)d_in[5];
    const float* fW1  = (const float*)d_in[6];
    const float* fb1  = (const float*)d_in[7];
    const float* fW2  = (const float*)d_in[8];
    const float* fb2  = (const float*)d_in[9];
    const float* iW1  = (const float*)d_in[10];
    const float* ib1  = (const float*)d_in[11];
    const float* iW2  = (const float*)d_in[12];
    const float* ib2  = (const float*)d_in[13];
    const float* gam  = (const float*)d_in[14];
    const float* bet  = (const float*)d_in[15];
    const float* oW1  = (const float*)d_in[16];
    const float* ob1  = (const float*)d_in[17];
    const float* og1  = (const float*)d_in[18];
    const float* obt1 = (const float*)d_in[19];
    const float* oW2  = (const float*)d_in[20];
    const float* ob2  = (const float*)d_in[21];
    const float* og2  = (const float*)d_in[22];
    const float* obt2 = (const float*)d_in[23];
    const float* fiW  = (const float*)d_in[24];
    const float* fib  = (const float*)d_in[25];
    float* out = (float*)d_out;

    table_kernel<<<(Ll * Kt) / 256, 256>>>(fW1, fb1, fW2, fb2);
    embed_kernel<<<(Nn * 16 + 255) / 256, 256>>>(x, embW, embB);
    hist_kernel<<<(Ee + 255) / 256, 256>>>(eidx);
    scan_kernel<<<NB1, 1024>>>();
    fill_kernel<<<(Ee + 255) / 256, 256>>>(eidx, dist);

    for (int l = 0; l < Ll; l++) {
        agg_kernel<<<(Nn * 32 + 255) / 256, 256>>>(l);
        int flags = (l == Ll - 1) ? 1 : 2;   // last: mean; else: write mirror
        node_mma_kernel<<<444, 128>>>(iW1 + l * 4096, ib1 + l * 64,
                                      iW2 + l * 4096, ib2 + l * 64,
                                      gam + l * 64, bet + l * 64, flags);
    }

    final_kernel<<<1, 64>>>(oW1, ob1, og1, obt1, oW2, ob2, og2, obt2,
                            fiW, fib, out);
}

// round 15
// speedup vs baseline: 1.6326x; 1.0489x over previous
#include <cuda_runtime.h>
#include <cuda_bf16.h>
#include <math.h>

#define Nn 100000
#define Ee 1600000
#define Hh 64
#define Ll 3
#define Kt 8192
#define CUT 5.0f
#define INVBN 0.9995003747f   // 1/sqrt(1+1e-3)
#define NB1 98                // ceil(Nn/1024) scan blocks
#define NTILE 6250            // Nn/16 node tiles

typedef unsigned long long ull;
typedef unsigned int u32;

// ---- static device scratch ----
__device__ __align__(256) float g_h[Nn * Hh];       // node features fp32, 25.6 MB
__device__ __align__(256) u32   g_hb[Nn * 32];      // bf16x2 gather mirror, 12.8 MB
__device__ __align__(256) u32   g_aggb[Nn * 32];    // bf16x2 agg result, 12.8 MB
__device__ __align__(256) int4  g_ep4[Ee];          // (col, fs0, fs1, fs2), 25.6 MB
__device__ int   g_cnt[Nn];                         // zero-init; re-zeroed by scan
__device__ int   g_off[Nn];
__device__ int   g_cur[Nn];                         // after fill: row END offsets
__device__ ull   g_state[NB1];                      // lookback scan states
__device__ float g_table[Ll * Kt];
__device__ float g_mean[Hh];

__device__ __forceinline__ float sp(float x) {      // softplus, stable
    return fmaxf(x, 0.0f) + log1pf(expf(-fabsf(x)));
}

// pack two f32 -> bf16x2 (lo in low 16 bits, hi in high 16 bits)
__device__ __forceinline__ u32 packbf(float lo, float hi) {
    u32 r;
    asm("cvt.rn.bf16x2.f32 %0, %1, %2;" : "=r"(r) : "f"(hi), "f"(lo));
    return r;
}
// unpack bf16x2 -> two f32 via pure ALU bit ops (NO F2F converts)
__device__ __forceinline__ float bflo(u32 r) { return __uint_as_float(r << 16); }
__device__ __forceinline__ float bfhi(u32 r) { return __uint_as_float(r & 0xffff0000u); }

__device__ __forceinline__ u32 smaddr(const void* p) {
    return (u32)__cvta_generic_to_shared(p);
}
__device__ __forceinline__ void ldsm4(u32* f, u32 addr) {
    asm volatile("ldmatrix.sync.aligned.m8n8.x4.shared.b16 {%0,%1,%2,%3},[%4];"
                 : "=r"(f[0]), "=r"(f[1]), "=r"(f[2]), "=r"(f[3]) : "r"(addr));
}
__device__ __forceinline__ void ldsm2t(u32& b0, u32& b1, u32 addr) {
    asm volatile("ldmatrix.sync.aligned.m8n8.x2.trans.shared.b16 {%0,%1},[%2];"
                 : "=r"(b0), "=r"(b1) : "r"(addr));
}
__device__ __forceinline__ void mma16816(float& d0, float& d1, float& d2, float& d3,
                                         const u32* a, u32 b0, u32 b1) {
    asm volatile("mma.sync.aligned.m16n8k16.row.col.f32.bf16.bf16.f32 "
                 "{%0,%1,%2,%3},{%4,%5,%6,%7},{%8,%9},{%0,%1,%2,%3};"
                 : "+f"(d0), "+f"(d1), "+f"(d2), "+f"(d3)
                 : "r"(a[0]), "r"(a[1]), "r"(a[2]), "r"(a[3]), "r"(b0), "r"(b1));
}

// ---- FUSED prep: table (blocks 0..95) + embed + hist + zero mean/state ----
// grid = 6250 x 256; t spans exactly Nn*16 == Ee threads.
__global__ void fused_prep_kernel(const float* __restrict__ x,
                                  const float* __restrict__ embW,
                                  const float* __restrict__ embB,
                                  const float* __restrict__ fW1,
                                  const float* __restrict__ fb1,
                                  const float* __restrict__ fW2,
                                  const float* __restrict__ fb2,
                                  const int* __restrict__ eidx) {
    __shared__ float sW[16 * 64];
    __shared__ float sb[64];
    __shared__ float sw2[64];
    __shared__ float sb2;
    int tid = threadIdx.x;
    int t = blockIdx.x * 256 + tid;
    int do_table = (blockIdx.x < (Ll * Kt) / 256);
    int l = t >> 13;                      // valid when do_table
    for (int i = tid; i < 16 * 64; i += 256) sW[i] = embW[i];
    if (tid < 64) sb[tid] = embB[tid];
    if (do_table) {
        if (tid < 64) {
            const float* p = fW2 + l * Hh * Hh + tid * Hh;
            float s = 0.0f;
            #pragma unroll
            for (int k = 0; k < Hh; k++) s += p[k];
            sw2[tid] = s;
        }
        if (tid == 64) {
            float s = 0.0f;
            for (int k = 0; k < Hh; k++) s += fb2[l * Hh + k];
            sb2 = s;
        }
    }
    __syncthreads();

    // side duties
    if (t < Hh) g_mean[t] = 0.0f;
    if (t < NB1) g_state[t] = 0ull;

    // hist (g_cnt is zero: zero-init first call, re-zeroed by scan afterwards)
    atomicAdd(&g_cnt[__ldg(eidx + t)], 1);

    // table
    if (do_table) {
        int k = t & (Kt - 1);
        float d = k * (CUT / (float)(Kt - 1));
        float s = d * (2.0f / CUT) - 1.0f;
        const float* w1 = fW1 + l * Hh;
        const float* b1 = fb1 + l * Hh;
        float acc = sb2;
        #pragma unroll 8
        for (int j = 0; j < Hh; j++)
            acc = fmaf(tanhf(fmaf(s, w1[j], b1[j])), sw2[j], acc);
        float cut = 0.5f * (cosf(d * (float)(M_PI / 5.0)) + 1.0f);
        g_table[t] = acc * cut;
    }

    // embed
    int n = t >> 4, q = t & 15, j0 = q * 4;
    const float* xr = x + n * 16;
    float4 acc = make_float4(sb[j0], sb[j0 + 1], sb[j0 + 2], sb[j0 + 3]);
    #pragma unroll
    for (int i = 0; i < 16; i++) {
        float xi = xr[i];
        acc.x = fmaf(xi, sW[i * 64 + j0 + 0], acc.x);
        acc.y = fmaf(xi, sW[i * 64 + j0 + 1], acc.y);
        acc.z = fmaf(xi, sW[i * 64 + j0 + 2], acc.z);
        acc.w = fmaf(xi, sW[i * 64 + j0 + 3], acc.w);
    }
    ((float4*)g_h)[t] = acc;
    g_hb[n * 32 + q * 2 + 0] = packbf(acc.x, acc.y);
    g_hb[n * 32 + q * 2 + 1] = packbf(acc.z, acc.w);
}

// ---- single-pass decoupled-lookback exclusive scan; re-zeroes g_cnt ----
__global__ void __launch_bounds__(1024) scan_kernel() {
    int bid = blockIdx.x;
    int i = bid * 1024 + threadIdx.x;
    int v = (i < Nn) ? g_cnt[i] : 0;
    int lane = threadIdx.x & 31, w = threadIdx.x >> 5;
    int x = v;
    #pragma unroll
    for (int off = 1; off < 32; off <<= 1) {
        int y = __shfl_up_sync(0xffffffff, x, off);
        if (lane >= off) x += y;
    }
    __shared__ int wsum[32], wpre[32];
    __shared__ int stotal, sprefix;
    if (lane == 31) wsum[w] = x;
    __syncthreads();
    if (threadIdx.x < 32) {
        int s = wsum[threadIdx.x];
        int xs = s;
        #pragma unroll
        for (int off = 1; off < 32; off <<= 1) {
            int y = __shfl_up_sync(0xffffffff, xs, off);
            if ((int)threadIdx.x >= off) xs += y;
        }
        wpre[threadIdx.x] = xs - s;
        if (threadIdx.x == 31) stotal = xs;
    }
    __syncthreads();
    int total = stotal;
    if (threadIdx.x == 0) {
        if (bid == 0) {
            sprefix = 0;
            atomicExch(&g_state[0], (2ull << 32) | (unsigned)total);
        } else {
            atomicExch(&g_state[bid], (1ull << 32) | (unsigned)total);
            ull run = 0;
            int p = bid - 1;
            while (true) {
                ull sv = atomicAdd(&g_state[p], 0ull);
                unsigned st = (unsigned)(sv >> 32);
                if (st == 0u) { __nanosleep(32); continue; }
                run += (unsigned)sv;
                if (st == 2u) break;
                p--;
            }
            sprefix = (int)run;
            atomicExch(&g_state[bid], (2ull << 32) | (unsigned)(run + total));
        }
    }
    __syncthreads();
    if (i < Nn) {
        int o = x - v + wpre[w] + sprefix;
        g_off[i] = o;
        g_cur[i] = o;
        g_cnt[i] = 0;                    // leave zeroed for next graph replay
    }
}

// scatter edges into CSR order; one int4 record (col, fs0, fs1, fs2)
// after this kernel g_cur[r] == row-end offset (used by agg as 'end')
__global__ void fill_kernel(const int* __restrict__ eidx,
                            const float* __restrict__ dist) {
    int e = blockIdx.x * blockDim.x + threadIdx.x;
    if (e >= Ee) return;
    int r = eidx[e];
    int c = eidx[Ee + e];
    float d = __ldg(dist + e);
    float u = d * ((float)(Kt - 1) / CUT);
    u = fminf(fmaxf(u, 0.0f), (float)(Kt - 2) + 0.999f);
    int i = (int)u;
    float fr = u - (float)i;
    float fs[Ll];
    #pragma unroll
    for (int l = 0; l < Ll; l++) {
        const float* tb = g_table + l * Kt;
        float t0 = __ldg(tb + i), t1 = __ldg(tb + i + 1);
        fs[l] = fmaf(fr, t1 - t0, t0);
    }
    int pos = atomicAdd(&g_cur[r], 1);
    g_ep4[pos] = make_int4(c, __float_as_int(fs[0]),
                           __float_as_int(fs[1]), __float_as_int(fs[2]));
}

// ============ per-layer edge aggregation: warp per row, bf16 gather ============
// (R14 form; row end read from g_cur)
__global__ void __launch_bounds__(256) agg_kernel(int l) {
    int gw = (blockIdx.x * 256 + threadIdx.x) >> 5;
    if (gw >= Nn) return;
    int lane = threadIdx.x & 31;
    int beg = g_off[gw], end = g_cur[gw];
    int deg = end - beg;
    float2 acc = make_float2(0.0f, 0.0f);
    const u32* hb = g_hb;
    for (int base = 0; base < deg; base += 32) {
        int rem = deg - base;
        if (rem > 32) rem = 32;
        int col_r = 0, fs_r = 0;
        if (lane < rem) {
            int4 m = __ldg(&g_ep4[beg + base + lane]);
            col_r = m.x;
            fs_r = (l == 0) ? m.y : (l == 1 ? m.z : m.w);
        }
        int d = 0;
        #pragma unroll 4
        for (; d + 4 <= rem; d += 4) {
            int c0 = __shfl_sync(0xffffffff, col_r, d + 0);
            int c1 = __shfl_sync(0xffffffff, col_r, d + 1);
            int c2 = __shfl_sync(0xffffffff, col_r, d + 2);
            int c3 = __shfl_sync(0xffffffff, col_r, d + 3);
            float f0 = __int_as_float(__shfl_sync(0xffffffff, fs_r, d + 0));
            float f1 = __int_as_float(__shfl_sync(0xffffffff, fs_r, d + 1));
            float f2 = __int_as_float(__shfl_sync(0xffffffff, fs_r, d + 2));
            float f3 = __int_as_float(__shfl_sync(0xffffffff, fs_r, d + 3));
            u32 r0 = __ldg(hb + c0 * 32 + lane);
            u32 r1 = __ldg(hb + c1 * 32 + lane);
            u32 r2 = __ldg(hb + c2 * 32 + lane);
            u32 r3 = __ldg(hb + c3 * 32 + lane);
            acc.x = fmaf(bflo(r0), f0, acc.x);
            acc.y = fmaf(bfhi(r0), f0, acc.y);
            acc.x = fmaf(bflo(r1), f1, acc.x);
            acc.y = fmaf(bfhi(r1), f1, acc.y);
            acc.x = fmaf(bflo(r2), f2, acc.x);
            acc.y = fmaf(bfhi(r2), f2, acc.y);
            acc.x = fmaf(bflo(r3), f3, acc.x);
            acc.y = fmaf(bfhi(r3), f3, acc.y);
        }
        for (; d < rem; d++) {
            int c0 = __shfl_sync(0xffffffff, col_r, d);
            float f0 = __int_as_float(__shfl_sync(0xffffffff, fs_r, d));
            u32 r0 = __ldg(hb + c0 * 32 + lane);
            acc.x = fmaf(bflo(r0), f0, acc.x);
            acc.y = fmaf(bfhi(r0), f0, acc.y);
        }
    }
    g_aggb[gw * 32 + lane] = packbf(acc.x, acc.y);
}

// ===== node MLP via tensor cores: warp = 16 nodes, bf16 mma, split weights ====
__global__ void __launch_bounds__(128) node_mma_kernel(
    const float* __restrict__ iW1, const float* __restrict__ ib1,
    const float* __restrict__ iW2, const float* __restrict__ ib2,
    const float* __restrict__ gam, const float* __restrict__ bet,
    int flags) {   // bit0: mean; bit1: write bf16 mirror
    __shared__ __align__(16) __nv_bfloat16 W1h[64 * 72], W1l[64 * 72];
    __shared__ __align__(16) __nv_bfloat16 W2h[64 * 72], W2l[64 * 72];
    __shared__ __align__(16) u32 AT[4][16 * 36];     // per-warp bf16 tile
    __shared__ float sb1[64], sb2[64], sgm[64], sbt[64], smean[64];
    int tid = threadIdx.x, wid = tid >> 5, lane = tid & 31;
    int do_mean = flags & 1, do_mir = flags & 2;
    for (int idx = tid; idx < 4096; idx += 128) {
        int i = idx >> 6, j = idx & 63;
        float w = iW1[idx];
        __nv_bfloat16 hi = __float2bfloat16_rn(w);
        W1h[i * 72 + j] = hi;
        W1l[i * 72 + j] = __float2bfloat16_rn(w - __bfloat162float(hi));
        w = iW2[idx];
        hi = __float2bfloat16_rn(w);
        W2h[i * 72 + j] = hi;
        W2l[i * 72 + j] = __float2bfloat16_rn(w - __bfloat162float(hi));
    }
    if (tid < 64) {
        sb1[tid] = ib1[tid]; sb2[tid] = ib2[tid];
        sgm[tid] = gam[tid] * INVBN; sbt[tid] = bet[tid];
        smean[tid] = 0.0f;
    }
    __syncthreads();

    u32 at_base = smaddr(&AT[wid][0]);
    u32 w1h_b = smaddr(W1h), w1l_b = smaddr(W1l);
    u32 w2h_b = smaddr(W2h), w2l_b = smaddr(W2l);
    int tid4 = lane & 3, gid = lane >> 2;
    u32 arow = at_base + (lane & 15) * 144 + ((lane >> 4) & 1) * 16;
    u32 brow_off = (lane & 15) * 144;   // k-row per lane for B ldmatrix

    float ms[16];
    #pragma unroll
    for (int k = 0; k < 16; k++) ms[k] = 0.0f;

    for (int tile = blockIdx.x * 4 + wid; tile < NTILE; tile += gridDim.x * 4) {
        int n0 = tile << 4;
        __syncwarp();
        // stage agg tile (already packed bf16) -> smem
        #pragma unroll
        for (int q = lane; q < 512; q += 32) {
            int row = q >> 5, p = q & 31;
            AT[wid][row * 36 + p] = __ldg(g_aggb + (n0 + row) * 32 + p);
        }
        __syncwarp();
        u32 a[4][4];
        #pragma unroll
        for (int kk = 0; kk < 4; kk++) ldsm4(a[kk], arow + kk * 32);
        __syncwarp();   // A frags in regs; AT buffer now reusable as Ts
        // GEMM1 + softplus -> Ts
        #pragma unroll
        for (int nn = 0; nn < 8; nn++) {
            float d0 = 0.f, d1 = 0.f, d2 = 0.f, d3 = 0.f;
            #pragma unroll
            for (int kk = 0; kk < 4; kk++) {
                u32 b0, b1;
                u32 ko = kk * 16 * 144 + brow_off + nn * 16;
                ldsm2t(b0, b1, w1h_b + ko);
                mma16816(d0, d1, d2, d3, a[kk], b0, b1);
                ldsm2t(b0, b1, w1l_b + ko);
                mma16816(d0, d1, d2, d3, a[kk], b0, b1);
            }
            int c0 = nn * 8 + tid4 * 2;
            float s0 = sp(d0 + sb1[c0]), s1 = sp(d1 + sb1[c0 + 1]);
            float s2 = sp(d2 + sb1[c0]), s3 = sp(d3 + sb1[c0 + 1]);
            AT[wid][gid * 36 + nn * 4 + tid4] = packbf(s0, s1);
            AT[wid][(gid + 8) * 36 + nn * 4 + tid4] = packbf(s2, s3);
        }
        __syncwarp();
        #pragma unroll
        for (int kk = 0; kk < 4; kk++) ldsm4(a[kk], arow + kk * 32);
        // GEMM2 + BN/residual epilogue (+ bf16 mirror for next layer's gather)
        #pragma unroll
        for (int nn = 0; nn < 8; nn++) {
            float d0 = 0.f, d1 = 0.f, d2 = 0.f, d3 = 0.f;
            #pragma unroll
            for (int kk = 0; kk < 4; kk++) {
                u32 b0, b1;
                u32 ko = kk * 16 * 144 + brow_off + nn * 16;
                ldsm2t(b0, b1, w2h_b + ko);
                mma16816(d0, d1, d2, d3, a[kk], b0, b1);
                ldsm2t(b0, b1, w2l_b + ko);
                mma16816(d0, d1, d2, d3, a[kk], b0, b1);
            }
            int c0 = nn * 8 + tid4 * 2;
            float2* hp0 = (float2*)(g_h + (n0 + gid) * 64 + c0);
            float2* hp1 = (float2*)(g_h + (n0 + gid + 8) * 64 + c0);
            float2 h0 = *hp0, h1 = *hp1;
            h0.x += fmaf(d0 + sb2[c0],     sgm[c0],     sbt[c0]);
            h0.y += fmaf(d1 + sb2[c0 + 1], sgm[c0 + 1], sbt[c0 + 1]);
            h1.x += fmaf(d2 + sb2[c0],     sgm[c0],     sbt[c0]);
            h1.y += fmaf(d3 + sb2[c0 + 1], sgm[c0 + 1], sbt[c0 + 1]);
            *hp0 = h0; *hp1 = h1;
            if (do_mir) {
                g_hb[(n0 + gid) * 32 + (c0 >> 1)] = packbf(h0.x, h0.y);
                g_hb[(n0 + gid + 8) * 32 + (c0 >> 1)] = packbf(h1.x, h1.y);
            }
            ms[nn * 2 + 0] += h0.x + h1.x;
            ms[nn * 2 + 1] += h0.y + h1.y;
        }
    }
    if (do_mean) {
        #pragma unroll
        for (int k = 0; k < 16; k++) {
            ms[k] += __shfl_xor_sync(0xffffffff, ms[k], 4);
            ms[k] += __shfl_xor_sync(0xffffffff, ms[k], 8);
            ms[k] += __shfl_xor_sync(0xffffffff, ms[k], 16);
        }
        if (lane < 4) {
            #pragma unroll
            for (int nn = 0; nn < 8; nn++) {
                atomicAdd(&smean[nn * 8 + lane * 2 + 0], ms[nn * 2 + 0]);
                atomicAdd(&smean[nn * 8 + lane * 2 + 1], ms[nn * 2 + 1]);
            }
        }
        __syncthreads();
        if (tid < 64) atomicAdd(&g_mean[tid], smean[tid]);
    }
}

// ---- final head ----
__global__ void final_kernel(const float* __restrict__ oW1, const float* __restrict__ ob1,
                             const float* __restrict__ og1, const float* __restrict__ obt1,
                             const float* __restrict__ oW2, const float* __restrict__ ob2,
                             const float* __restrict__ og2, const float* __restrict__ obt2,
                             const float* __restrict__ fiW, const float* __restrict__ fib,
                             float* __restrict__ out) {
    __shared__ float gv[64], s1[32], s2[32];
    int t = threadIdx.x;  // 64 threads
    gv[t] = g_mean[t] * (1.0f / (float)Nn);
    __syncthreads();
    if (t < 32) {
        float acc = ob1[t];
        #pragma unroll
        for (int i = 0; i < 64; i++) acc = fmaf(gv[i], oW1[i * 32 + t], acc);
        s1[t] = fmaf(sp(acc) * INVBN, og1[t], obt1[t]);
    }
    __syncthreads();
    if (t < 32) {
        float acc = ob2[t];
        #pragma unroll
        for (int i = 0; i < 32; i++) acc = fmaf(s1[i], oW2[i * 32 + t], acc);
        s2[t] = fmaf(sp(acc) * INVBN, og2[t], obt2[t]);
    }
    __syncthreads();
    if (t < 3) {
        float acc = fib[t];
        #pragma unroll
        for (int i = 0; i < 32; i++) acc = fmaf(s2[i], fiW[i * 3 + t], acc);
        out[t] = acc;
    }
}

extern "C" void kernel_launch(void* const* d_in, const int* in_sizes, int n_in,
                              void* d_out, int out_size) {
    const float* x    = (const float*)d_in[0];
    const int*   eidx = (const int*)  d_in[1];
    const float* dist = (const float*)d_in[2];
    const float* embW = (const float*)d_in[4];
    const float* embB = (const float*)d_in[5];
    const float* fW1  = (const float*)d_in[6];
    const float* fb1  = (const float*)d_in[7];
    const float* fW2  = (const float*)d_in[8];
    const float* fb2  = (const float*)d_in[9];
    const float* iW1  = (const float*)d_in[10];
    const float* ib1  = (const float*)d_in[11];
    const float* iW2  = (const float*)d_in[12];
    const float* ib2  = (const float*)d_in[13];
    const float* gam  = (const float*)d_in[14];
    const float* bet  = (const float*)d_in[15];
    const float* oW1  = (const float*)d_in[16];
    const float* ob1  = (const float*)d_in[17];
    const float* og1  = (const float*)d_in[18];
    const float* obt1 = (const float*)d_in[19];
    const float* oW2  = (const float*)d_in[20];
    const float* ob2  = (const float*)d_in[21];
    const float* og2  = (const float*)d_in[22];
    const float* obt2 = (const float*)d_in[23];
    const float* fiW  = (const float*)d_in[24];
    const float* fib  = (const float*)d_in[25];
    float* out = (float*)d_out;

    fused_prep_kernel<<<(Nn * 16 + 255) / 256, 256>>>(x, embW, embB,
                                                      fW1, fb1, fW2, fb2, eidx);
    scan_kernel<<<NB1, 1024>>>();
    fill_kernel<<<(Ee + 255) / 256, 256>>>(eidx, dist);

    for (int l = 0; l < Ll; l++) {
        agg_kernel<<<(Nn * 32 + 255) / 256, 256>>>(l);   // l=0 at launch idx 3
        int flags = (l == Ll - 1) ? 1 : 2;   // last: mean; else: write mirror
        node_mma_kernel<<<444, 128>>>(iW1 + l * 4096, ib1 + l * 64,
                                      iW2 + l * 4096, ib2 + l * 64,
                                      gam + l * 64, bet + l * 64, flags);
    }

    final_kernel<<<1, 64>>>(oW1, ob1, og1, obt1, oW2, ob2, og2, obt2,
                            fiW, fib, out);
}